// round 9
// baseline (speedup 1.0000x reference)
#include <cuda_runtime.h>
#include <cuda_bf16.h>
#include <cstddef>

#define SEQ   4096
#define DIMX  128
#define BT    64
#define NCH   64
#define BHMAX 32

#define PADA  132   // ≡4 (mod 32)
#define PADB  136   // ≡8 (mod 32)
#define PADS  72    // ≡8 (mod 32)

__device__ float g_state[BHMAX * NCH * DIMX * DIMX];
__device__ float g_cum[BHMAX * SEQ];
__device__ float g_tot[BHMAX * NCH];

__device__ __forceinline__ unsigned f2tf(float x) {
    unsigned u;
    asm("cvt.rna.tf32.f32 %0, %1;" : "=r"(u) : "f"(x));
    return u;
}

__device__ __forceinline__ void mma8(float c[4], unsigned a0, unsigned a1,
                                     unsigned a2, unsigned a3,
                                     unsigned b0, unsigned b1) {
    asm("mma.sync.aligned.m16n8k8.row.col.f32.tf32.tf32.f32 "
        "{%0,%1,%2,%3},{%4,%5,%6,%7},{%8,%9},{%0,%1,%2,%3};"
        : "+f"(c[0]), "+f"(c[1]), "+f"(c[2]), "+f"(c[3])
        : "r"(a0), "r"(a1), "r"(a2), "r"(a3), "r"(b0), "r"(b1));
}

// ───────────── Pass 0: beta log-cumsum per chunk ─────────────
__global__ __launch_bounds__(32)
void pass_beta(const float* __restrict__ beta)
{
    const int lane = threadIdx.x;
    const int c = blockIdx.x, bh = blockIdx.y;
    const float* betab = beta + (size_t)bh * SEQ + c * BT;

    float b0 = logf(betab[lane]      + 1e-6f);
    float b1 = logf(betab[32 + lane] + 1e-6f);
    #pragma unroll
    for (int off = 1; off < 32; off <<= 1) {
        float n = __shfl_up_sync(0xffffffffu, b0, off);
        if (lane >= off) b0 += n;
    }
    float t0 = __shfl_sync(0xffffffffu, b0, 31);
    #pragma unroll
    for (int off = 1; off < 32; off <<= 1) {
        float n = __shfl_up_sync(0xffffffffu, b1, off);
        if (lane >= off) b1 += n;
    }
    float c1  = t0 + b1;
    float tot = __shfl_sync(0xffffffffu, c1, 31);
    g_cum[bh * SEQ + c * BT + lane]      = b0;
    g_cum[bh * SEQ + c * BT + 32 + lane] = c1;
    if (lane == 0) g_tot[bh * NCH + c] = tot;
}

// ───────────── Pass A: upd_c[d][e] = Σ_j k[j][d]·dte[j]·v[j][e] ─────────────
__global__ __launch_bounds__(256, 2)
void pass_upd(const float* __restrict__ k, const float* __restrict__ v)
{
    extern __shared__ unsigned smu[];
    unsigned* sk  = smu;              // [64][PADB]
    unsigned* sve = sk + 64 * PADB;   // [64][PADB]
    float* dte = (float*)(sve + 64 * PADB);

    const int t = threadIdx.x, lane = t & 31, w = t >> 5;
    const int g = lane >> 2, tg = lane & 3;
    const int c = blockIdx.x, bh = blockIdx.y;

    if (t < 64) {
        float tot = g_tot[bh * NCH + c];
        dte[t] = __expf(tot - g_cum[bh * SEQ + c * BT + t]);
    }
    __syncthreads();

    const float* kb = k + ((size_t)bh * SEQ + c * BT) * DIMX;
    const float* vb = v + ((size_t)bh * SEQ + c * BT) * DIMX;
    #pragma unroll
    for (int it = 0; it < 8; ++it) {
        int p = t + it * 256;
        int j = p >> 5, f = p & 31;
        float4 kk = *(const float4*)(kb + (size_t)j * DIMX + 4 * f);
        *(uint4*)(sk + j * PADB + 4 * f) = uint4{f2tf(kk.x), f2tf(kk.y), f2tf(kk.z), f2tf(kk.w)};
        float4 vv = *(const float4*)(vb + (size_t)j * DIMX + 4 * f);
        float dd = dte[j];
        *(uint4*)(sve + j * PADB + 4 * f) =
            uint4{f2tf(vv.x * dd), f2tf(vv.y * dd), f2tf(vv.z * dd), f2tf(vv.w * dd)};
    }
    __syncthreads();

    const int d0w = 32 * (w >> 1), e0w = 64 * (w & 1);
    float acc[2][8][4];
    #pragma unroll
    for (int mt = 0; mt < 2; ++mt)
        #pragma unroll
        for (int nt = 0; nt < 8; ++nt)
            #pragma unroll
            for (int r = 0; r < 4; ++r) acc[mt][nt][r] = 0.0f;

    #pragma unroll
    for (int ks = 0; ks < 8; ++ks) {
        int j0 = 8 * ks;
        unsigned a[2][4];
        #pragma unroll
        for (int mt = 0; mt < 2; ++mt) {
            int db = d0w + 16 * mt;
            a[mt][0] = sk[(j0 + tg) * PADB + db + g];
            a[mt][1] = sk[(j0 + tg) * PADB + db + 8 + g];
            a[mt][2] = sk[(j0 + tg + 4) * PADB + db + g];
            a[mt][3] = sk[(j0 + tg + 4) * PADB + db + 8 + g];
        }
        #pragma unroll
        for (int nt = 0; nt < 8; ++nt) {
            int eb = e0w + 8 * nt;
            unsigned b0 = sve[(j0 + tg) * PADB + eb + g];
            unsigned b1 = sve[(j0 + tg + 4) * PADB + eb + g];
            mma8(acc[0][nt], a[0][0], a[0][1], a[0][2], a[0][3], b0, b1);
            mma8(acc[1][nt], a[1][0], a[1][1], a[1][2], a[1][3], b0, b1);
        }
    }

    float* dst = g_state + (((size_t)(bh * NCH + c)) << 14);
    #pragma unroll
    for (int mt = 0; mt < 2; ++mt) {
        int d = d0w + 16 * mt + g;
        #pragma unroll
        for (int nt = 0; nt < 8; ++nt) {
            int e = e0w + 8 * nt + 2 * tg;
            *(float2*)(dst + d * DIMX + e)       = float2{acc[mt][nt][0], acc[mt][nt][1]};
            *(float2*)(dst + (d + 8) * DIMX + e) = float2{acc[mt][nt][2], acc[mt][nt][3]};
        }
    }
}

// ───────────── Pass B: in-place scan upd → S_before ─────────────
__global__ __launch_bounds__(256)
void pass_scan()
{
    __shared__ float et[NCH];
    const int t = threadIdx.x;
    const int seg = blockIdx.x, bh = blockIdx.y;
    if (t < NCH) et[t] = __expf(g_tot[bh * NCH + t]);
    __syncthreads();

    const size_t base = ((size_t)bh * NCH) << 14;
    const int off = seg * 1024 + 4 * t;
    float4 s = {0.f, 0.f, 0.f, 0.f};
    #pragma unroll 2
    for (int c = 0; c < NCH; ++c) {
        float* p = g_state + base + ((size_t)c << 14) + off;
        float4 u = *(const float4*)p;
        *(float4*)p = s;
        float e = et[c];
        s.x = s.x * e + u.x;
        s.y = s.y * e + u.y;
        s.z = s.z * e + u.z;
        s.w = s.w * e + u.w;
    }
}

// ───────────── Pass C1: out = (QKᵀ⊙decay)@V  (intra-chunk) ─────────────
__global__ __launch_bounds__(256, 2)
void pass_intra(const float* __restrict__ q, const float* __restrict__ k,
                const float* __restrict__ v, float* __restrict__ out)
{
    extern __shared__ unsigned smu[];
    unsigned* sq  = smu;               // [64][PADA] tf32 q
    unsigned* skA = sq + 64 * PADA;    // [64][PADA] tf32 k, then A
    unsigned* sv  = skA + 64 * PADA;   // [64][PADB] tf32 v
    float* cum = (float*)(sv + 64 * PADB);  // [64]

    const int t = threadIdx.x, lane = t & 31, w = t >> 5;
    const int g = lane >> 2, tg = lane & 3;
    const int wi = w >> 1, half = w & 1;
    const int i0 = 16 * wi;
    const int c = blockIdx.x, bh = blockIdx.y;
    const size_t cb = ((size_t)bh * SEQ + (size_t)c * BT) * DIMX;

    if (t < 64) cum[t] = g_cum[bh * SEQ + c * BT + t];
    {
        const float* qrow = q + cb;
        const float* krow = k + cb;
        const float* vrow = v + cb;
        #pragma unroll
        for (int it = 0; it < 8; ++it) {
            int p = t + it * 256;
            int j = p >> 5, f = p & 31;
            float4 vq = *(const float4*)(qrow + (size_t)j * DIMX + 4 * f);
            *(uint4*)(sq + j * PADA + 4 * f) = uint4{f2tf(vq.x), f2tf(vq.y), f2tf(vq.z), f2tf(vq.w)};
            float4 vk = *(const float4*)(krow + (size_t)j * DIMX + 4 * f);
            *(uint4*)(skA + j * PADA + 4 * f) = uint4{f2tf(vk.x), f2tf(vk.y), f2tf(vk.z), f2tf(vk.w)};
            float4 vv = *(const float4*)(vrow + (size_t)j * DIMX + 4 * f);
            *(uint4*)(sv + j * PADB + 4 * f) = uint4{f2tf(vv.x), f2tf(vv.y), f2tf(vv.z), f2tf(vv.w)};
        }
    }
    __syncthreads();

    // ── QKᵀ with causal nt-tile skip ──
    const int j0w = 32 * half;
    float s[4][4];
    #pragma unroll
    for (int nt = 0; nt < 4; ++nt)
        #pragma unroll
        for (int r = 0; r < 4; ++r) s[nt][r] = 0.0f;

    #pragma unroll 4
    for (int kk = 0; kk < 16; ++kk) {
        int d0 = 8 * kk;
        unsigned a0 = sq[(i0 + g) * PADA + d0 + tg];
        unsigned a1 = sq[(i0 + g + 8) * PADA + d0 + tg];
        unsigned a2 = sq[(i0 + g) * PADA + d0 + tg + 4];
        unsigned a3 = sq[(i0 + g + 8) * PADA + d0 + tg + 4];
        #pragma unroll
        for (int nt = 0; nt < 4; ++nt) {
            int j0 = j0w + 8 * nt;
            if (j0 <= i0 + 15) {
                unsigned b0 = skA[(j0 + g) * PADA + d0 + tg];
                unsigned b1 = skA[(j0 + g) * PADA + d0 + tg + 4];
                mma8(s[nt], a0, a1, a2, a3, b0, b1);
            }
        }
    }

    // mask + decay
    float m[4][4];
    {
        int iL = i0 + g, iH = i0 + g + 8;
        float ciL = cum[iL], ciH = cum[iH];
        #pragma unroll
        for (int nt = 0; nt < 4; ++nt) {
            int jA = j0w + 8 * nt + 2 * tg, jB = jA + 1;
            float cjA = cum[jA], cjB = cum[jB];
            m[nt][0] = (jA <= iL) ? s[nt][0] * __expf(ciL - cjA) : 0.0f;
            m[nt][1] = (jB <= iL) ? s[nt][1] * __expf(ciL - cjB) : 0.0f;
            m[nt][2] = (jA <= iH) ? s[nt][2] * __expf(ciH - cjA) : 0.0f;
            m[nt][3] = (jB <= iH) ? s[nt][3] * __expf(ciH - cjB) : 0.0f;
        }
    }
    __syncthreads();   // all k reads complete — safe to overwrite skA with A
    #pragma unroll
    for (int nt = 0; nt < 4; ++nt) {
        int j0 = j0w + 8 * nt;
        if (j0 <= i0 + 15) {
            skA[(i0 + g) * PADA + j0 + 2 * tg]         = f2tf(m[nt][0]);
            skA[(i0 + g) * PADA + j0 + 2 * tg + 1]     = f2tf(m[nt][1]);
            skA[(i0 + g + 8) * PADA + j0 + 2 * tg]     = f2tf(m[nt][2]);
            skA[(i0 + g + 8) * PADA + j0 + 2 * tg + 1] = f2tf(m[nt][3]);
        }
    }
    __syncthreads();   // publish A

    // ── A @ V with causal ks truncation ──
    const int e0w = 64 * half;
    float o[8][4];
    #pragma unroll
    for (int nt = 0; nt < 8; ++nt)
        #pragma unroll
        for (int r = 0; r < 4; ++r) o[nt][r] = 0.0f;

    const int kmax = 2 * wi + 2;
    for (int ks = 0; ks < kmax; ++ks) {
        int j0 = 8 * ks;
        unsigned a0 = skA[(i0 + g) * PADA + j0 + tg];
        unsigned a1 = skA[(i0 + g + 8) * PADA + j0 + tg];
        unsigned a2 = skA[(i0 + g) * PADA + j0 + tg + 4];
        unsigned a3 = skA[(i0 + g + 8) * PADA + j0 + tg + 4];
        #pragma unroll
        for (int nt = 0; nt < 8; ++nt) {
            int e0 = e0w + 8 * nt;
            unsigned b0 = sv[(j0 + tg) * PADB + e0 + g];
            unsigned b1 = sv[(j0 + tg + 4) * PADB + e0 + g];
            mma8(o[nt], a0, a1, a2, a3, b0, b1);
        }
    }

    float* dst = out + cb;
    #pragma unroll
    for (int nt = 0; nt < 8; ++nt) {
        int e = e0w + 8 * nt + 2 * tg;
        int i = i0 + g;
        *(float2*)(dst + (size_t)i * DIMX + e)       = float2{o[nt][0], o[nt][1]};
        *(float2*)(dst + (size_t)(i + 8) * DIMX + e) = float2{o[nt][2], o[nt][3]};
    }
}

// ───────────── Pass C2: out += dfs ⊙ (Q @ S_half)  (inter-chunk) ─────────────
__global__ __launch_bounds__(256, 3)
void pass_inter(const float* __restrict__ q, float* __restrict__ out)
{
    extern __shared__ unsigned smu[];
    unsigned* sq = smu;              // [64][PADA] tf32 q
    unsigned* sS = sq + 64 * PADA;   // [128][PADS] tf32 state half
    float* dfs = (float*)(sS + 128 * PADS);  // [64]

    const int t = threadIdx.x, lane = t & 31, w = t >> 5;
    const int g = lane >> 2, tg = lane & 3;
    const int wi = w >> 1, half = w & 1;
    const int i0 = 16 * wi;
    const int eh = blockIdx.x, c = blockIdx.y, bh = blockIdx.z;
    const int e0h = 64 * eh;
    const size_t cb = ((size_t)bh * SEQ + (size_t)c * BT) * DIMX;

    if (t < 64) dfs[t] = __expf(g_cum[bh * SEQ + c * BT + t]);
    {
        const float* qrow = q + cb;
        #pragma unroll
        for (int it = 0; it < 8; ++it) {
            int p = t + it * 256;
            int j = p >> 5, f = p & 31;
            float4 vq = *(const float4*)(qrow + (size_t)j * DIMX + 4 * f);
            *(uint4*)(sq + j * PADA + 4 * f) = uint4{f2tf(vq.x), f2tf(vq.y), f2tf(vq.z), f2tf(vq.w)};
        }
        const float* sb = g_state + (((size_t)(bh * NCH + c)) << 14) + e0h;
        #pragma unroll
        for (int it = 0; it < 8; ++it) {
            int p = t + it * 256;            // 0..2047
            int row = p >> 4, cf = p & 15;
            float4 u = *(const float4*)(sb + ((size_t)row << 7) + 4 * cf);
            *(uint4*)(sS + row * PADS + 4 * cf) = uint4{f2tf(u.x), f2tf(u.y), f2tf(u.z), f2tf(u.w)};
        }
    }
    __syncthreads();

    const int e0w = 32 * half;
    float o[4][4];
    #pragma unroll
    for (int nt = 0; nt < 4; ++nt)
        #pragma unroll
        for (int r = 0; r < 4; ++r) o[nt][r] = 0.0f;

    #pragma unroll 4
    for (int kk = 0; kk < 16; ++kk) {
        int d0 = 8 * kk;
        unsigned a0 = sq[(i0 + g) * PADA + d0 + tg];
        unsigned a1 = sq[(i0 + g + 8) * PADA + d0 + tg];
        unsigned a2 = sq[(i0 + g) * PADA + d0 + tg + 4];
        unsigned a3 = sq[(i0 + g + 8) * PADA + d0 + tg + 4];
        #pragma unroll
        for (int nt = 0; nt < 4; ++nt) {
            int e0 = e0w + 8 * nt;
            unsigned b0 = sS[(d0 + tg) * PADS + e0 + g];
            unsigned b1 = sS[(d0 + tg + 4) * PADS + e0 + g];
            mma8(o[nt], a0, a1, a2, a3, b0, b1);
        }
    }

    float fL = dfs[i0 + g], fH = dfs[i0 + g + 8];
    float* dst = out + cb + e0h;
    #pragma unroll
    for (int nt = 0; nt < 4; ++nt) {
        int e = e0w + 8 * nt + 2 * tg;
        int i = i0 + g;
        float2 aL = *(const float2*)(dst + (size_t)i * DIMX + e);
        float2 aH = *(const float2*)(dst + (size_t)(i + 8) * DIMX + e);
        aL.x += fL * o[nt][0]; aL.y += fL * o[nt][1];
        aH.x += fH * o[nt][2]; aH.y += fH * o[nt][3];
        *(float2*)(dst + (size_t)i * DIMX + e)       = aL;
        *(float2*)(dst + (size_t)(i + 8) * DIMX + e) = aH;
    }
}

extern "C" void kernel_launch(void* const* d_in, const int* in_sizes, int n_in,
                              void* d_out, int out_size)
{
    const float* q    = (const float*)d_in[0];
    const float* k    = (const float*)d_in[1];
    const float* v    = (const float*)d_in[2];
    const float* beta = (const float*)d_in[3];
    float* out = (float*)d_out;

    // lazy one-time stream/event creation (first call is the non-captured
    // correctness run; capture calls reuse the same handles)
    static cudaStream_t s2 = nullptr;
    static cudaEvent_t  eF = nullptr, eJ = nullptr;
    static bool inited = false;
    if (!inited) {
        cudaStreamCreateWithFlags(&s2, cudaStreamNonBlocking);
        cudaEventCreateWithFlags(&eF, cudaEventDisableTiming);
        cudaEventCreateWithFlags(&eJ, cudaEventDisableTiming);
        const size_t smemA  = (size_t)(64 * PADB * 2) * 4 + 64 * 4 + 64;
        const size_t smemC1 = (size_t)(64 * PADA * 2 + 64 * PADB) * 4 + 64 * 4 + 64;
        const size_t smemC2 = (size_t)(64 * PADA + 128 * PADS) * 4 + 64 * 4 + 64;
        cudaFuncSetAttribute(pass_upd,   cudaFuncAttributeMaxDynamicSharedMemorySize, (int)smemA);
        cudaFuncSetAttribute(pass_intra, cudaFuncAttributeMaxDynamicSharedMemorySize, (int)smemC1);
        cudaFuncSetAttribute(pass_inter, cudaFuncAttributeMaxDynamicSharedMemorySize, (int)smemC2);
        inited = true;
    }

    const size_t smemA  = (size_t)(64 * PADB * 2) * 4 + 64 * 4 + 64;
    const size_t smemC1 = (size_t)(64 * PADA * 2 + 64 * PADB) * 4 + 64 * 4 + 64;
    const size_t smemC2 = (size_t)(64 * PADA + 128 * PADS) * 4 + 64 * 4 + 64;

    // beta cumsum first (both branches depend on it)
    dim3 g0(NCH, BHMAX);
    pass_beta<<<g0, 32>>>(beta);

    // fork: intra on s2, upd+scan on origin
    cudaEventRecord(eF, 0);
    cudaStreamWaitEvent(s2, eF, 0);

    dim3 gC1(NCH, BHMAX);
    pass_intra<<<gC1, 256, smemC1, s2>>>(q, k, v, out);
    cudaEventRecord(eJ, s2);

    dim3 gA(NCH, BHMAX);
    pass_upd<<<gA, 256, smemA>>>(k, v);

    dim3 gB(16, BHMAX);
    pass_scan<<<gB, 256>>>();

    // join: inter needs both scan (state) and intra (out base values)
    cudaStreamWaitEvent(0, eJ, 0);

    dim3 gC2(2, NCH, BHMAX);
    pass_inter<<<gC2, 256, smemC2>>>(q, out);
}

// round 14
// speedup vs baseline: 1.8549x; 1.8549x over previous
#include <cuda_runtime.h>
#include <cuda_bf16.h>
#include <cstddef>

#define SEQ   4096
#define DIMX  128
#define BT    64
#define NCH   64
#define BHMAX 32

#define PADA  132   // ≡4 (mod 32)
#define PADB  136   // ≡8 (mod 32)
#define PADS  72    // ≡8 (mod 32)

__device__ float g_state[BHMAX * NCH * DIMX * DIMX];  // upd matrices (pass_upd out)
__device__ float g_sbef [BHMAX * NCH * DIMX * DIMX];  // S_before     (pass_scan out)
__device__ float g_cum[BHMAX * SEQ];
__device__ float g_tot[BHMAX * NCH];

__device__ __forceinline__ unsigned f2tf(float x) {
    unsigned u;
    asm("cvt.rna.tf32.f32 %0, %1;" : "=r"(u) : "f"(x));
    return u;
}

__device__ __forceinline__ void mma8(float c[4], unsigned a0, unsigned a1,
                                     unsigned a2, unsigned a3,
                                     unsigned b0, unsigned b1) {
    asm("mma.sync.aligned.m16n8k8.row.col.f32.tf32.tf32.f32 "
        "{%0,%1,%2,%3},{%4,%5,%6,%7},{%8,%9},{%0,%1,%2,%3};"
        : "+f"(c[0]), "+f"(c[1]), "+f"(c[2]), "+f"(c[3])
        : "r"(a0), "r"(a1), "r"(a2), "r"(a3), "r"(b0), "r"(b1));
}

// ───────────── Pass 0: beta log-cumsum per chunk ─────────────
__global__ __launch_bounds__(32)
void pass_beta(const float* __restrict__ beta)
{
    const int lane = threadIdx.x;
    const int c = blockIdx.x, bh = blockIdx.y;
    const float* betab = beta + (size_t)bh * SEQ + c * BT;

    float b0 = logf(betab[lane]      + 1e-6f);
    float b1 = logf(betab[32 + lane] + 1e-6f);
    #pragma unroll
    for (int off = 1; off < 32; off <<= 1) {
        float n = __shfl_up_sync(0xffffffffu, b0, off);
        if (lane >= off) b0 += n;
    }
    float t0 = __shfl_sync(0xffffffffu, b0, 31);
    #pragma unroll
    for (int off = 1; off < 32; off <<= 1) {
        float n = __shfl_up_sync(0xffffffffu, b1, off);
        if (lane >= off) b1 += n;
    }
    float c1  = t0 + b1;
    float tot = __shfl_sync(0xffffffffu, c1, 31);
    g_cum[bh * SEQ + c * BT + lane]      = b0;
    g_cum[bh * SEQ + c * BT + 32 + lane] = c1;
    if (lane == 0) g_tot[bh * NCH + c] = tot;
}

// ───────────── Pass A: upd_c[d][e] = Σ_j k[j][d]·dte[j]·v[j][e] ─────────────
__global__ __launch_bounds__(256, 2)
void pass_upd(const float* __restrict__ k, const float* __restrict__ v)
{
    extern __shared__ unsigned smu[];
    unsigned* sk  = smu;              // [64][PADB]
    unsigned* sve = sk + 64 * PADB;   // [64][PADB]
    float* dte = (float*)(sve + 64 * PADB);

    const int t = threadIdx.x, lane = t & 31, w = t >> 5;
    const int g = lane >> 2, tg = lane & 3;
    const int c = blockIdx.x, bh = blockIdx.y;

    if (t < 64) {
        float tot = g_tot[bh * NCH + c];
        dte[t] = __expf(tot - g_cum[bh * SEQ + c * BT + t]);
    }
    __syncthreads();

    const float* kb = k + ((size_t)bh * SEQ + c * BT) * DIMX;
    const float* vb = v + ((size_t)bh * SEQ + c * BT) * DIMX;
    #pragma unroll
    for (int it = 0; it < 8; ++it) {
        int p = t + it * 256;
        int j = p >> 5, f = p & 31;
        float4 kk = *(const float4*)(kb + (size_t)j * DIMX + 4 * f);
        *(uint4*)(sk + j * PADB + 4 * f) = uint4{f2tf(kk.x), f2tf(kk.y), f2tf(kk.z), f2tf(kk.w)};
        float4 vv = *(const float4*)(vb + (size_t)j * DIMX + 4 * f);
        float dd = dte[j];
        *(uint4*)(sve + j * PADB + 4 * f) =
            uint4{f2tf(vv.x * dd), f2tf(vv.y * dd), f2tf(vv.z * dd), f2tf(vv.w * dd)};
    }
    __syncthreads();

    const int d0w = 32 * (w >> 1), e0w = 64 * (w & 1);
    float acc[2][8][4];
    #pragma unroll
    for (int mt = 0; mt < 2; ++mt)
        #pragma unroll
        for (int nt = 0; nt < 8; ++nt)
            #pragma unroll
            for (int r = 0; r < 4; ++r) acc[mt][nt][r] = 0.0f;

    #pragma unroll
    for (int ks = 0; ks < 8; ++ks) {
        int j0 = 8 * ks;
        unsigned a[2][4];
        #pragma unroll
        for (int mt = 0; mt < 2; ++mt) {
            int db = d0w + 16 * mt;
            a[mt][0] = sk[(j0 + tg) * PADB + db + g];
            a[mt][1] = sk[(j0 + tg) * PADB + db + 8 + g];
            a[mt][2] = sk[(j0 + tg + 4) * PADB + db + g];
            a[mt][3] = sk[(j0 + tg + 4) * PADB + db + 8 + g];
        }
        #pragma unroll
        for (int nt = 0; nt < 8; ++nt) {
            int eb = e0w + 8 * nt;
            unsigned b0 = sve[(j0 + tg) * PADB + eb + g];
            unsigned b1 = sve[(j0 + tg + 4) * PADB + eb + g];
            mma8(acc[0][nt], a[0][0], a[0][1], a[0][2], a[0][3], b0, b1);
            mma8(acc[1][nt], a[1][0], a[1][1], a[1][2], a[1][3], b0, b1);
        }
    }

    float* dst = g_state + (((size_t)(bh * NCH + c)) << 14);
    #pragma unroll
    for (int mt = 0; mt < 2; ++mt) {
        int d = d0w + 16 * mt + g;
        #pragma unroll
        for (int nt = 0; nt < 8; ++nt) {
            int e = e0w + 8 * nt + 2 * tg;
            *(float2*)(dst + d * DIMX + e)       = float2{acc[mt][nt][0], acc[mt][nt][1]};
            *(float2*)(dst + (d + 8) * DIMX + e) = float2{acc[mt][nt][2], acc[mt][nt][3]};
        }
    }
}

// ───────────── Pass B: scan g_state (upd) → g_sbef (S_before) ─────────────
// Distinct src/dst arrays + 4-deep manual prefetch pipeline → high MLP.
__global__ __launch_bounds__(256)
void pass_scan()
{
    __shared__ float et[NCH];
    const int t = threadIdx.x;
    const int seg = blockIdx.x, bh = blockIdx.y;
    if (t < NCH) et[t] = __expf(g_tot[bh * NCH + t]);
    __syncthreads();

    const size_t base = ((size_t)bh * NCH) << 14;
    const int off = seg * 1024 + 4 * t;
    const float* src = g_state + base + off;
    float*       dst = g_sbef  + base + off;

    // prefetch queue depth 4
    float4 u0 = *(const float4*)(src);
    float4 u1 = *(const float4*)(src + (1 << 14));
    float4 u2 = *(const float4*)(src + (2 << 14));
    float4 u3 = *(const float4*)(src + (3 << 14));

    float4 s = {0.f, 0.f, 0.f, 0.f};
    #pragma unroll 4
    for (int c = 0; c < NCH; ++c) {
        float4 u = u0;
        u0 = u1; u1 = u2; u2 = u3;
        if (c + 4 < NCH) u3 = *(const float4*)(src + ((size_t)(c + 4) << 14));
        *(float4*)(dst + ((size_t)c << 14)) = s;
        float e = et[c];
        s.x = s.x * e + u.x;
        s.y = s.y * e + u.y;
        s.z = s.z * e + u.z;
        s.w = s.w * e + u.w;
    }
}

// ───────────── Pass C1: out = (QKᵀ⊙decay)@V  (intra-chunk) ─────────────
__global__ __launch_bounds__(256, 2)
void pass_intra(const float* __restrict__ q, const float* __restrict__ k,
                const float* __restrict__ v, float* __restrict__ out)
{
    extern __shared__ unsigned smu[];
    unsigned* sq  = smu;               // [64][PADA] tf32 q
    unsigned* skA = sq + 64 * PADA;    // [64][PADA] tf32 k, then A
    unsigned* sv  = skA + 64 * PADA;   // [64][PADB] tf32 v
    float* cum = (float*)(sv + 64 * PADB);  // [64]

    const int t = threadIdx.x, lane = t & 31, w = t >> 5;
    const int g = lane >> 2, tg = lane & 3;
    const int wi = w >> 1, half = w & 1;
    const int i0 = 16 * wi;
    const int c = blockIdx.x, bh = blockIdx.y;
    const size_t cb = ((size_t)bh * SEQ + (size_t)c * BT) * DIMX;

    if (t < 64) cum[t] = g_cum[bh * SEQ + c * BT + t];
    {
        const float* qrow = q + cb;
        const float* krow = k + cb;
        const float* vrow = v + cb;
        #pragma unroll
        for (int it = 0; it < 8; ++it) {
            int p = t + it * 256;
            int j = p >> 5, f = p & 31;
            float4 vq = *(const float4*)(qrow + (size_t)j * DIMX + 4 * f);
            *(uint4*)(sq + j * PADA + 4 * f) = uint4{f2tf(vq.x), f2tf(vq.y), f2tf(vq.z), f2tf(vq.w)};
            float4 vk = *(const float4*)(krow + (size_t)j * DIMX + 4 * f);
            *(uint4*)(skA + j * PADA + 4 * f) = uint4{f2tf(vk.x), f2tf(vk.y), f2tf(vk.z), f2tf(vk.w)};
            float4 vv = *(const float4*)(vrow + (size_t)j * DIMX + 4 * f);
            *(uint4*)(sv + j * PADB + 4 * f) = uint4{f2tf(vv.x), f2tf(vv.y), f2tf(vv.z), f2tf(vv.w)};
        }
    }
    __syncthreads();

    // ── QKᵀ with causal nt-tile skip ──
    const int j0w = 32 * half;
    float s[4][4];
    #pragma unroll
    for (int nt = 0; nt < 4; ++nt)
        #pragma unroll
        for (int r = 0; r < 4; ++r) s[nt][r] = 0.0f;

    #pragma unroll 4
    for (int kk = 0; kk < 16; ++kk) {
        int d0 = 8 * kk;
        unsigned a0 = sq[(i0 + g) * PADA + d0 + tg];
        unsigned a1 = sq[(i0 + g + 8) * PADA + d0 + tg];
        unsigned a2 = sq[(i0 + g) * PADA + d0 + tg + 4];
        unsigned a3 = sq[(i0 + g + 8) * PADA + d0 + tg + 4];
        #pragma unroll
        for (int nt = 0; nt < 4; ++nt) {
            int j0 = j0w + 8 * nt;
            if (j0 <= i0 + 15) {
                unsigned b0 = skA[(j0 + g) * PADA + d0 + tg];
                unsigned b1 = skA[(j0 + g) * PADA + d0 + tg + 4];
                mma8(s[nt], a0, a1, a2, a3, b0, b1);
            }
        }
    }

    // mask + decay
    float m[4][4];
    {
        int iL = i0 + g, iH = i0 + g + 8;
        float ciL = cum[iL], ciH = cum[iH];
        #pragma unroll
        for (int nt = 0; nt < 4; ++nt) {
            int jA = j0w + 8 * nt + 2 * tg, jB = jA + 1;
            float cjA = cum[jA], cjB = cum[jB];
            m[nt][0] = (jA <= iL) ? s[nt][0] * __expf(ciL - cjA) : 0.0f;
            m[nt][1] = (jB <= iL) ? s[nt][1] * __expf(ciL - cjB) : 0.0f;
            m[nt][2] = (jA <= iH) ? s[nt][2] * __expf(ciH - cjA) : 0.0f;
            m[nt][3] = (jB <= iH) ? s[nt][3] * __expf(ciH - cjB) : 0.0f;
        }
    }
    __syncthreads();   // all k reads complete — safe to overwrite skA with A
    #pragma unroll
    for (int nt = 0; nt < 4; ++nt) {
        int j0 = j0w + 8 * nt;
        if (j0 <= i0 + 15) {
            skA[(i0 + g) * PADA + j0 + 2 * tg]         = f2tf(m[nt][0]);
            skA[(i0 + g) * PADA + j0 + 2 * tg + 1]     = f2tf(m[nt][1]);
            skA[(i0 + g + 8) * PADA + j0 + 2 * tg]     = f2tf(m[nt][2]);
            skA[(i0 + g + 8) * PADA + j0 + 2 * tg + 1] = f2tf(m[nt][3]);
        }
    }
    __syncthreads();   // publish A

    // ── A @ V with causal ks truncation ──
    const int e0w = 64 * half;
    float o[8][4];
    #pragma unroll
    for (int nt = 0; nt < 8; ++nt)
        #pragma unroll
        for (int r = 0; r < 4; ++r) o[nt][r] = 0.0f;

    const int kmax = 2 * wi + 2;
    for (int ks = 0; ks < kmax; ++ks) {
        int j0 = 8 * ks;
        unsigned a0 = skA[(i0 + g) * PADA + j0 + tg];
        unsigned a1 = skA[(i0 + g + 8) * PADA + j0 + tg];
        unsigned a2 = skA[(i0 + g) * PADA + j0 + tg + 4];
        unsigned a3 = skA[(i0 + g + 8) * PADA + j0 + tg + 4];
        #pragma unroll
        for (int nt = 0; nt < 8; ++nt) {
            int e0 = e0w + 8 * nt;
            unsigned b0 = sv[(j0 + tg) * PADB + e0 + g];
            unsigned b1 = sv[(j0 + tg + 4) * PADB + e0 + g];
            mma8(o[nt], a0, a1, a2, a3, b0, b1);
        }
    }

    float* dst = out + cb;
    #pragma unroll
    for (int nt = 0; nt < 8; ++nt) {
        int e = e0w + 8 * nt + 2 * tg;
        int i = i0 + g;
        *(float2*)(dst + (size_t)i * DIMX + e)       = float2{o[nt][0], o[nt][1]};
        *(float2*)(dst + (size_t)(i + 8) * DIMX + e) = float2{o[nt][2], o[nt][3]};
    }
}

// ───────────── Pass C2: out += dfs ⊙ (Q @ S_half)  (inter-chunk) ─────────────
__global__ __launch_bounds__(256, 3)
void pass_inter(const float* __restrict__ q, float* __restrict__ out)
{
    extern __shared__ unsigned smu[];
    unsigned* sq = smu;              // [64][PADA] tf32 q
    unsigned* sS = sq + 64 * PADA;   // [128][PADS] tf32 state half
    float* dfs = (float*)(sS + 128 * PADS);  // [64]

    const int t = threadIdx.x, lane = t & 31, w = t >> 5;
    const int g = lane >> 2, tg = lane & 3;
    const int wi = w >> 1, half = w & 1;
    const int i0 = 16 * wi;
    const int eh = blockIdx.x, c = blockIdx.y, bh = blockIdx.z;
    const int e0h = 64 * eh;
    const size_t cb = ((size_t)bh * SEQ + (size_t)c * BT) * DIMX;

    if (t < 64) dfs[t] = __expf(g_cum[bh * SEQ + c * BT + t]);
    {
        const float* qrow = q + cb;
        #pragma unroll
        for (int it = 0; it < 8; ++it) {
            int p = t + it * 256;
            int j = p >> 5, f = p & 31;
            float4 vq = *(const float4*)(qrow + (size_t)j * DIMX + 4 * f);
            *(uint4*)(sq + j * PADA + 4 * f) = uint4{f2tf(vq.x), f2tf(vq.y), f2tf(vq.z), f2tf(vq.w)};
        }
        const float* sb = g_sbef + (((size_t)(bh * NCH + c)) << 14) + e0h;
        #pragma unroll
        for (int it = 0; it < 8; ++it) {
            int p = t + it * 256;            // 0..2047
            int row = p >> 4, cf = p & 15;
            float4 u = *(const float4*)(sb + ((size_t)row << 7) + 4 * cf);
            *(uint4*)(sS + row * PADS + 4 * cf) = uint4{f2tf(u.x), f2tf(u.y), f2tf(u.z), f2tf(u.w)};
        }
    }
    __syncthreads();

    const int e0w = 32 * half;
    float o[4][4];
    #pragma unroll
    for (int nt = 0; nt < 4; ++nt)
        #pragma unroll
        for (int r = 0; r < 4; ++r) o[nt][r] = 0.0f;

    #pragma unroll 4
    for (int kk = 0; kk < 16; ++kk) {
        int d0 = 8 * kk;
        unsigned a0 = sq[(i0 + g) * PADA + d0 + tg];
        unsigned a1 = sq[(i0 + g + 8) * PADA + d0 + tg];
        unsigned a2 = sq[(i0 + g) * PADA + d0 + tg + 4];
        unsigned a3 = sq[(i0 + g + 8) * PADA + d0 + tg + 4];
        #pragma unroll
        for (int nt = 0; nt < 4; ++nt) {
            int e0 = e0w + 8 * nt;
            unsigned b0 = sS[(d0 + tg) * PADS + e0 + g];
            unsigned b1 = sS[(d0 + tg + 4) * PADS + e0 + g];
            mma8(o[nt], a0, a1, a2, a3, b0, b1);
        }
    }

    float fL = dfs[i0 + g], fH = dfs[i0 + g + 8];
    float* dst = out + cb + e0h;
    #pragma unroll
    for (int nt = 0; nt < 4; ++nt) {
        int e = e0w + 8 * nt + 2 * tg;
        int i = i0 + g;
        float2 aL = *(const float2*)(dst + (size_t)i * DIMX + e);
        float2 aH = *(const float2*)(dst + (size_t)(i + 8) * DIMX + e);
        aL.x += fL * o[nt][0]; aL.y += fL * o[nt][1];
        aH.x += fH * o[nt][2]; aH.y += fH * o[nt][3];
        *(float2*)(dst + (size_t)i * DIMX + e)       = aL;
        *(float2*)(dst + (size_t)(i + 8) * DIMX + e) = aH;
    }
}

extern "C" void kernel_launch(void* const* d_in, const int* in_sizes, int n_in,
                              void* d_out, int out_size)
{
    const float* q    = (const float*)d_in[0];
    const float* k    = (const float*)d_in[1];
    const float* v    = (const float*)d_in[2];
    const float* beta = (const float*)d_in[3];
    float* out = (float*)d_out;

    static cudaStream_t s2 = nullptr;
    static cudaEvent_t  eF = nullptr, eJ = nullptr;
    static bool inited = false;
    if (!inited) {
        cudaStreamCreateWithFlags(&s2, cudaStreamNonBlocking);
        cudaEventCreateWithFlags(&eF, cudaEventDisableTiming);
        cudaEventCreateWithFlags(&eJ, cudaEventDisableTiming);
        const size_t smemA  = (size_t)(64 * PADB * 2) * 4 + 64 * 4 + 64;
        const size_t smemC1 = (size_t)(64 * PADA * 2 + 64 * PADB) * 4 + 64 * 4 + 64;
        const size_t smemC2 = (size_t)(64 * PADA + 128 * PADS) * 4 + 64 * 4 + 64;
        cudaFuncSetAttribute(pass_upd,   cudaFuncAttributeMaxDynamicSharedMemorySize, (int)smemA);
        cudaFuncSetAttribute(pass_intra, cudaFuncAttributeMaxDynamicSharedMemorySize, (int)smemC1);
        cudaFuncSetAttribute(pass_inter, cudaFuncAttributeMaxDynamicSharedMemorySize, (int)smemC2);
        inited = true;
    }

    const size_t smemA  = (size_t)(64 * PADB * 2) * 4 + 64 * 4 + 64;
    const size_t smemC1 = (size_t)(64 * PADA * 2 + 64 * PADB) * 4 + 64 * 4 + 64;
    const size_t smemC2 = (size_t)(64 * PADA + 128 * PADS) * 4 + 64 * 4 + 64;

    // beta cumsum first (both branches depend on it)
    dim3 g0(NCH, BHMAX);
    pass_beta<<<g0, 32>>>(beta);

    // fork: intra on s2, upd+scan on origin
    cudaEventRecord(eF, 0);
    cudaStreamWaitEvent(s2, eF, 0);

    dim3 gC1(NCH, BHMAX);
    pass_intra<<<gC1, 256, smemC1, s2>>>(q, k, v, out);
    cudaEventRecord(eJ, s2);

    dim3 gA(NCH, BHMAX);
    pass_upd<<<gA, 256, smemA>>>(k, v);

    dim3 gB(16, BHMAX);
    pass_scan<<<gB, 256>>>();

    // join: inter needs both scan (S_before) and intra (out base values)
    cudaStreamWaitEvent(0, eJ, 0);

    dim3 gC2(2, NCH, BHMAX);
    pass_inter<<<gC2, 256, smemC2>>>(q, out);
}

// round 17
// speedup vs baseline: 2.0617x; 1.1115x over previous
#include <cuda_runtime.h>
#include <cuda_bf16.h>
#include <cstddef>

#define SEQ   4096
#define DIMX  128
#define BT    64
#define NCH   64
#define BHMAX 32

#define PADA  132   // ≡4 (mod 32)
#define PADB  136   // ≡8 (mod 32)
#define PADS  136   // f32 state rows

__device__ float g_state[BHMAX * NCH * DIMX * DIMX];  // upd matrices
__device__ float g_sbef [BHMAX * NCH * DIMX * DIMX];  // S_before
__device__ float g_cum[BHMAX * SEQ];
__device__ float g_tot[BHMAX * NCH];

__device__ __forceinline__ unsigned f2tf(float x) {
    unsigned u;
    asm("cvt.rna.tf32.f32 %0, %1;" : "=r"(u) : "f"(x));
    return u;
}

__device__ __forceinline__ void mma8(float c[4], unsigned a0, unsigned a1,
                                     unsigned a2, unsigned a3,
                                     unsigned b0, unsigned b1) {
    asm("mma.sync.aligned.m16n8k8.row.col.f32.tf32.tf32.f32 "
        "{%0,%1,%2,%3},{%4,%5,%6,%7},{%8,%9},{%0,%1,%2,%3};"
        : "+f"(c[0]), "+f"(c[1]), "+f"(c[2]), "+f"(c[3])
        : "r"(a0), "r"(a1), "r"(a2), "r"(a3), "r"(b0), "r"(b1));
}

// ───────────── Pass 0: beta log-cumsum per chunk ─────────────
__global__ __launch_bounds__(32)
void pass_beta(const float* __restrict__ beta)
{
    const int lane = threadIdx.x;
    const int c = blockIdx.x, bh = blockIdx.y;
    const float* betab = beta + (size_t)bh * SEQ + c * BT;

    float b0 = logf(betab[lane]      + 1e-6f);
    float b1 = logf(betab[32 + lane] + 1e-6f);
    #pragma unroll
    for (int off = 1; off < 32; off <<= 1) {
        float n = __shfl_up_sync(0xffffffffu, b0, off);
        if (lane >= off) b0 += n;
    }
    float t0 = __shfl_sync(0xffffffffu, b0, 31);
    #pragma unroll
    for (int off = 1; off < 32; off <<= 1) {
        float n = __shfl_up_sync(0xffffffffu, b1, off);
        if (lane >= off) b1 += n;
    }
    float c1  = t0 + b1;
    float tot = __shfl_sync(0xffffffffu, c1, 31);
    g_cum[bh * SEQ + c * BT + lane]      = b0;
    g_cum[bh * SEQ + c * BT + 32 + lane] = c1;
    if (lane == 0) g_tot[bh * NCH + c] = tot;
}

// ───────────── Pass A: upd_c[d][e] = Σ_j k[j][d]·dte[j]·v[j][e] ─────────────
__global__ __launch_bounds__(256, 2)
void pass_upd(const float* __restrict__ k, const float* __restrict__ v)
{
    extern __shared__ unsigned smu[];
    unsigned* sk  = smu;              // [64][PADB]
    unsigned* sve = sk + 64 * PADB;   // [64][PADB]
    float* dte = (float*)(sve + 64 * PADB);

    const int t = threadIdx.x, lane = t & 31, w = t >> 5;
    const int g = lane >> 2, tg = lane & 3;
    const int c = blockIdx.x, bh = blockIdx.y;

    if (t < 64) {
        float tot = g_tot[bh * NCH + c];
        dte[t] = __expf(tot - g_cum[bh * SEQ + c * BT + t]);
    }
    __syncthreads();

    const float* kb = k + ((size_t)bh * SEQ + c * BT) * DIMX;
    const float* vb = v + ((size_t)bh * SEQ + c * BT) * DIMX;
    #pragma unroll
    for (int it = 0; it < 8; ++it) {
        int p = t + it * 256;
        int j = p >> 5, f = p & 31;
        float4 kk = *(const float4*)(kb + (size_t)j * DIMX + 4 * f);
        *(uint4*)(sk + j * PADB + 4 * f) = uint4{f2tf(kk.x), f2tf(kk.y), f2tf(kk.z), f2tf(kk.w)};
        float4 vv = *(const float4*)(vb + (size_t)j * DIMX + 4 * f);
        float dd = dte[j];
        *(uint4*)(sve + j * PADB + 4 * f) =
            uint4{f2tf(vv.x * dd), f2tf(vv.y * dd), f2tf(vv.z * dd), f2tf(vv.w * dd)};
    }
    __syncthreads();

    const int d0w = 32 * (w >> 1), e0w = 64 * (w & 1);
    float acc[2][8][4];
    #pragma unroll
    for (int mt = 0; mt < 2; ++mt)
        #pragma unroll
        for (int nt = 0; nt < 8; ++nt)
            #pragma unroll
            for (int r = 0; r < 4; ++r) acc[mt][nt][r] = 0.0f;

    #pragma unroll
    for (int ks = 0; ks < 8; ++ks) {
        int j0 = 8 * ks;
        unsigned a[2][4];
        #pragma unroll
        for (int mt = 0; mt < 2; ++mt) {
            int db = d0w + 16 * mt;
            a[mt][0] = sk[(j0 + tg) * PADB + db + g];
            a[mt][1] = sk[(j0 + tg) * PADB + db + 8 + g];
            a[mt][2] = sk[(j0 + tg + 4) * PADB + db + g];
            a[mt][3] = sk[(j0 + tg + 4) * PADB + db + 8 + g];
        }
        #pragma unroll
        for (int nt = 0; nt < 8; ++nt) {
            int eb = e0w + 8 * nt;
            unsigned b0 = sve[(j0 + tg) * PADB + eb + g];
            unsigned b1 = sve[(j0 + tg + 4) * PADB + eb + g];
            mma8(acc[0][nt], a[0][0], a[0][1], a[0][2], a[0][3], b0, b1);
            mma8(acc[1][nt], a[1][0], a[1][1], a[1][2], a[1][3], b0, b1);
        }
    }

    float* dst = g_state + (((size_t)(bh * NCH + c)) << 14);
    #pragma unroll
    for (int mt = 0; mt < 2; ++mt) {
        int d = d0w + 16 * mt + g;
        #pragma unroll
        for (int nt = 0; nt < 8; ++nt) {
            int e = e0w + 8 * nt + 2 * tg;
            *(float2*)(dst + d * DIMX + e)       = float2{acc[mt][nt][0], acc[mt][nt][1]};
            *(float2*)(dst + (d + 8) * DIMX + e) = float2{acc[mt][nt][2], acc[mt][nt][3]};
        }
    }
}

// ───────────── Pass B: scan g_state (upd) → g_sbef (S_before), MLP-pipelined ─────────────
__global__ __launch_bounds__(256)
void pass_scan()
{
    __shared__ float et[NCH];
    const int t = threadIdx.x;
    const int seg = blockIdx.x, bh = blockIdx.y;
    if (t < NCH) et[t] = __expf(g_tot[bh * NCH + t]);
    __syncthreads();

    const size_t base = ((size_t)bh * NCH) << 14;
    const int off = seg * 1024 + 4 * t;
    const float* src = g_state + base + off;
    float*       dst = g_sbef  + base + off;

    float4 u0 = *(const float4*)(src);
    float4 u1 = *(const float4*)(src + (1 << 14));
    float4 u2 = *(const float4*)(src + (2 << 14));
    float4 u3 = *(const float4*)(src + (3 << 14));

    float4 s = {0.f, 0.f, 0.f, 0.f};
    #pragma unroll 4
    for (int c = 0; c < NCH; ++c) {
        float4 u = u0;
        u0 = u1; u1 = u2; u2 = u3;
        if (c + 4 < NCH) u3 = *(const float4*)(src + ((size_t)(c + 4) << 14));
        *(float4*)(dst + ((size_t)c << 14)) = s;
        float e = et[c];
        s.x = s.x * e + u.x;
        s.y = s.y * e + u.y;
        s.z = s.z * e + u.z;
        s.w = s.w * e + u.w;
    }
}

// ───────────── Pass C (fused): out = (QKᵀ⊙decay)@V + dfs⊙(Q@S_before) ─────────────
// Full S tile prefetched via cp.async at CTA start; latency hidden under QKᵀ phase.
__global__ __launch_bounds__(256, 1)
void pass_out(const float* __restrict__ q, const float* __restrict__ k,
              const float* __restrict__ v, float* __restrict__ out)
{
    extern __shared__ unsigned smu[];
    unsigned* sq  = smu;               // [64][PADA] tf32 q
    unsigned* skA = sq + 64 * PADA;    // [64][PADA] tf32 k, then A
    unsigned* sv  = skA + 64 * PADA;   // [64][PADB] tf32 v
    float*    sS  = (float*)(sv + 64 * PADB);  // [128][PADS] f32 S_before (cp.async)
    float* cum = (float*)(sS + 128 * PADS);    // [64]
    float* dfs = cum + 64;                     // [64]

    const int t = threadIdx.x, lane = t & 31, w = t >> 5;
    const int g = lane >> 2, tg = lane & 3;
    const int wi = w >> 1, half = w & 1;
    const int i0 = 16 * wi;
    const int c = blockIdx.x, bh = blockIdx.y;
    const size_t cb = ((size_t)bh * SEQ + (size_t)c * BT) * DIMX;

    // ── 1. kick off full-state prefetch (64 KB) via cp.async ──
    {
        const size_t sbase = ((size_t)(bh * NCH + c)) << 14;
        #pragma unroll
        for (int it = 0; it < 16; ++it) {
            int p = t + it * 256;            // 0..4095 chunks of 16B
            int row = p >> 5, ch = p & 31;
            unsigned dstb = (unsigned)__cvta_generic_to_shared(sS + row * PADS + 4 * ch);
            const float* src = g_sbef + sbase + ((size_t)row << 7) + 4 * ch;
            asm volatile("cp.async.cg.shared.global [%0], [%1], 16;\n"
                         :: "r"(dstb), "l"(src));
        }
        asm volatile("cp.async.commit_group;\n" ::: "memory");
    }

    if (t < 64) {
        float cc = g_cum[bh * SEQ + c * BT + t];
        cum[t] = cc;
        dfs[t] = __expf(cc);
    }
    {
        const float* qrow = q + cb;
        const float* krow = k + cb;
        const float* vrow = v + cb;
        #pragma unroll
        for (int it = 0; it < 8; ++it) {
            int p = t + it * 256;
            int j = p >> 5, f = p & 31;
            float4 vq = *(const float4*)(qrow + (size_t)j * DIMX + 4 * f);
            *(uint4*)(sq + j * PADA + 4 * f) = uint4{f2tf(vq.x), f2tf(vq.y), f2tf(vq.z), f2tf(vq.w)};
            float4 vk = *(const float4*)(krow + (size_t)j * DIMX + 4 * f);
            *(uint4*)(skA + j * PADA + 4 * f) = uint4{f2tf(vk.x), f2tf(vk.y), f2tf(vk.z), f2tf(vk.w)};
            float4 vv = *(const float4*)(vrow + (size_t)j * DIMX + 4 * f);
            *(uint4*)(sv + j * PADB + 4 * f) = uint4{f2tf(vv.x), f2tf(vv.y), f2tf(vv.z), f2tf(vv.w)};
        }
    }
    __syncthreads();

    // ── 2. extract Q fragments once (reused by QKᵀ and Q@S) ──
    unsigned qa[16][4];
    #pragma unroll
    for (int kk = 0; kk < 16; ++kk) {
        int d0 = 8 * kk;
        qa[kk][0] = sq[(i0 + g) * PADA + d0 + tg];
        qa[kk][1] = sq[(i0 + g + 8) * PADA + d0 + tg];
        qa[kk][2] = sq[(i0 + g) * PADA + d0 + tg + 4];
        qa[kk][3] = sq[(i0 + g + 8) * PADA + d0 + tg + 4];
    }

    // ── 3. QKᵀ with causal nt-tile skip ──
    const int j0w = 32 * half;
    float s[4][4];
    #pragma unroll
    for (int nt = 0; nt < 4; ++nt)
        #pragma unroll
        for (int r = 0; r < 4; ++r) s[nt][r] = 0.0f;

    #pragma unroll
    for (int nt = 0; nt < 4; ++nt) {
        int j0 = j0w + 8 * nt;
        if (j0 <= i0 + 15) {
            #pragma unroll
            for (int kk = 0; kk < 16; ++kk) {
                int d0 = 8 * kk;
                unsigned b0 = skA[(j0 + g) * PADA + d0 + tg];
                unsigned b1 = skA[(j0 + g) * PADA + d0 + tg + 4];
                mma8(s[nt], qa[kk][0], qa[kk][1], qa[kk][2], qa[kk][3], b0, b1);
            }
        }
    }

    // mask + decay in registers
    float m[4][4];
    {
        int iL = i0 + g, iH = i0 + g + 8;
        float ciL = cum[iL], ciH = cum[iH];
        #pragma unroll
        for (int nt = 0; nt < 4; ++nt) {
            int jA = j0w + 8 * nt + 2 * tg, jB = jA + 1;
            float cjA = cum[jA], cjB = cum[jB];
            m[nt][0] = (jA <= iL) ? s[nt][0] * __expf(ciL - cjA) : 0.0f;
            m[nt][1] = (jB <= iL) ? s[nt][1] * __expf(ciL - cjB) : 0.0f;
            m[nt][2] = (jA <= iH) ? s[nt][2] * __expf(ciH - cjA) : 0.0f;
            m[nt][3] = (jB <= iH) ? s[nt][3] * __expf(ciH - cjB) : 0.0f;
        }
    }
    __syncthreads();   // all k reads complete — safe to overwrite skA with A

    #pragma unroll
    for (int nt = 0; nt < 4; ++nt) {
        int j0 = j0w + 8 * nt;
        if (j0 <= i0 + 15) {
            skA[(i0 + g) * PADA + j0 + 2 * tg]         = f2tf(m[nt][0]);
            skA[(i0 + g) * PADA + j0 + 2 * tg + 1]     = f2tf(m[nt][1]);
            skA[(i0 + g + 8) * PADA + j0 + 2 * tg]     = f2tf(m[nt][2]);
            skA[(i0 + g + 8) * PADA + j0 + 2 * tg + 1] = f2tf(m[nt][3]);
        }
    }

    // ── 4. wait for state prefetch, then inter: Q @ S_before ──
    asm volatile("cp.async.wait_group 0;\n" ::: "memory");
    __syncthreads();   // also publishes A stores above

    const int e0w = 64 * half;
    float o[8][4];
    #pragma unroll
    for (int nt = 0; nt < 8; ++nt)
        #pragma unroll
        for (int r = 0; r < 4; ++r) o[nt][r] = 0.0f;

    #pragma unroll 4
    for (int kk = 0; kk < 16; ++kk) {
        int dl = 8 * kk;
        #pragma unroll
        for (int nt = 0; nt < 8; ++nt) {
            int e0 = e0w + 8 * nt;
            unsigned b0 = f2tf(sS[(dl + tg) * PADS + e0 + g]);
            unsigned b1 = f2tf(sS[(dl + tg + 4) * PADS + e0 + g]);
            mma8(o[nt], qa[kk][0], qa[kk][1], qa[kk][2], qa[kk][3], b0, b1);
        }
    }
    {
        float fL = dfs[i0 + g], fH = dfs[i0 + g + 8];
        #pragma unroll
        for (int nt = 0; nt < 8; ++nt) {
            o[nt][0] *= fL; o[nt][1] *= fL;
            o[nt][2] *= fH; o[nt][3] *= fH;
        }
    }

    // ── 5. intra: A @ V with causal ks truncation ──
    const int kmax = 2 * wi + 2;
    for (int ks = 0; ks < kmax; ++ks) {
        int j0 = 8 * ks;
        unsigned a0 = skA[(i0 + g) * PADA + j0 + tg];
        unsigned a1 = skA[(i0 + g + 8) * PADA + j0 + tg];
        unsigned a2 = skA[(i0 + g) * PADA + j0 + tg + 4];
        unsigned a3 = skA[(i0 + g + 8) * PADA + j0 + tg + 4];
        #pragma unroll
        for (int nt = 0; nt < 8; ++nt) {
            int e0 = e0w + 8 * nt;
            unsigned b0 = sv[(j0 + tg) * PADB + e0 + g];
            unsigned b1 = sv[(j0 + tg + 4) * PADB + e0 + g];
            mma8(o[nt], a0, a1, a2, a3, b0, b1);
        }
    }

    float* dst = out + cb;
    #pragma unroll
    for (int nt = 0; nt < 8; ++nt) {
        int e = e0w + 8 * nt + 2 * tg;
        int i = i0 + g;
        *(float2*)(dst + (size_t)i * DIMX + e)       = float2{o[nt][0], o[nt][1]};
        *(float2*)(dst + (size_t)(i + 8) * DIMX + e) = float2{o[nt][2], o[nt][3]};
    }
}

extern "C" void kernel_launch(void* const* d_in, const int* in_sizes, int n_in,
                              void* d_out, int out_size)
{
    const float* q    = (const float*)d_in[0];
    const float* k    = (const float*)d_in[1];
    const float* v    = (const float*)d_in[2];
    const float* beta = (const float*)d_in[3];
    float* out = (float*)d_out;

    const size_t smemA = (size_t)(64 * PADB * 2) * 4 + 64 * 4 + 64;
    const size_t smemC = (size_t)(64 * PADA * 2 + 64 * PADB + 128 * PADS) * 4 + 128 * 4 + 64;
    cudaFuncSetAttribute(pass_upd, cudaFuncAttributeMaxDynamicSharedMemorySize, (int)smemA);
    cudaFuncSetAttribute(pass_out, cudaFuncAttributeMaxDynamicSharedMemorySize, (int)smemC);

    dim3 g0(NCH, BHMAX);
    pass_beta<<<g0, 32>>>(beta);

    dim3 gA(NCH, BHMAX);
    pass_upd<<<gA, 256, smemA>>>(k, v);

    dim3 gB(16, BHMAX);
    pass_scan<<<gB, 256>>>();

    dim3 gC(NCH, BHMAX);
    pass_out<<<gC, 256, smemC>>>(q, k, v, out);
}